// round 15
// baseline (speedup 1.0000x reference)
#include <cuda_runtime.h>
#include <cuda_bf16.h>
#include <cstdint>

// Problem: B=4, H=W=64 -> N=4096, C=64, Cf=8
#define BATCH 4
#define NTOK  4096
#define CDIM  64
#define CF    8
#define BN    (BATCH * NTOK)
#define KT    64               // keys per tile
#define NTILE (NTOK / KT)      // 64
#define QPC   64               // queries per CTA (4 warps x 16)
#define HP    72               // hS pitch (elements) - conflict-free for ldmatrix
#define STG   4                // cp.async pipeline stages

// ---------------- scratch (no cudaMalloc allowed) ----------------
__device__ __nv_bfloat16 d_fb[BN * CF];              // keys    [B,N,8]
__device__ __nv_bfloat16 d_gb[BN * CF];              // queries [B,N,8] (pre-scaled by log2e)
__device__ __nv_bfloat16 d_htb[BATCH * CDIM * NTOK]; // values transposed [B,C,N]
__device__ unsigned int  d_bar = 0;                  // device-wide barrier ticket

#define MMA16816(d, a0, a1, a2, a3, b0, b1, c) \
    asm volatile("mma.sync.aligned.m16n8k16.row.col.f32.bf16.bf16.f32 " \
        "{%0,%1,%2,%3}, {%4,%5,%6,%7}, {%8,%9}, {%10,%11,%12,%13};" \
        : "=f"((d)[0]), "=f"((d)[1]), "=f"((d)[2]), "=f"((d)[3]) \
        : "r"(a0), "r"(a1), "r"(a2), "r"(a3), "r"(b0), "r"(b1), \
          "f"((c)[0]), "f"((c)[1]), "f"((c)[2]), "f"((c)[3]))

#define MMA1688(d, a0, a1, b0, c) \
    asm volatile("mma.sync.aligned.m16n8k8.row.col.f32.bf16.bf16.f32 " \
        "{%0,%1,%2,%3}, {%4,%5}, {%6}, {%7,%8,%9,%10};" \
        : "=f"((d)[0]), "=f"((d)[1]), "=f"((d)[2]), "=f"((d)[3]) \
        : "r"(a0), "r"(a1), "r"(b0), \
          "f"((c)[0]), "f"((c)[1]), "f"((c)[2]), "f"((c)[3]))

#define CVT_BF16X2(res, lo, hi) \
    asm("cvt.rn.bf16x2.f32 %0, %1, %2;" : "=r"(res) : "f"(hi), "f"(lo))

__device__ __forceinline__ float ex2f(float v) {
    float r;
    asm("ex2.approx.f32 %0, %1;" : "=f"(r) : "f"(v));
    return r;
}

__device__ __forceinline__ void cp16(void* dst, const void* src) {
    const uint32_t d = (uint32_t)__cvta_generic_to_shared(dst);
    asm volatile("cp.async.cg.shared.global [%0], [%1], 16;" :: "r"(d), "l"(src));
}
#define CP_COMMIT() asm volatile("cp.async.commit_group;" ::: "memory")
#define CP_WAIT0()  asm volatile("cp.async.wait_group 0;" ::: "memory")

__device__ __forceinline__ void ldmat4(uint32_t& r0, uint32_t& r1, uint32_t& r2,
                                       uint32_t& r3, const void* p) {
    const uint32_t a = (uint32_t)__cvta_generic_to_shared(p);
    asm volatile("ldmatrix.sync.aligned.m8n8.x4.shared.b16 {%0,%1,%2,%3}, [%4];"
                 : "=r"(r0), "=r"(r1), "=r"(r2), "=r"(r3) : "r"(a));
}

// shared-memory overlay (40960 bytes)
#define SM_BYTES 40960
#define P_WFT 0
#define P_WGT 2176
#define P_WHT 4352
#define P_BF  21760
#define P_BG  21792
#define P_BH  21824
#define P_XS  22080
#define P_HS  30784

__global__ __launch_bounds__(128, 2)
void fused_kernel(const float* __restrict__ x,
                  const float* __restrict__ w_f, const float* __restrict__ b_f,
                  const float* __restrict__ w_g, const float* __restrict__ b_g,
                  const float* __restrict__ w_h, const float* __restrict__ b_h,
                  const float* __restrict__ gamma,
                  float* __restrict__ out) {
    __shared__ __align__(16) char smraw[SM_BYTES];

    const int tid = threadIdx.x;

    // ================= phase 1: projections =================
    {
        float* wfT = (float*)(smraw + P_WFT);
        float* wgT = (float*)(smraw + P_WGT);
        float* whT = (float*)(smraw + P_WHT);
        float* bfs = (float*)(smraw + P_BF);
        float* bgs = (float*)(smraw + P_BG);
        float* bhs = (float*)(smraw + P_BH);
        float* xs  = (float*)(smraw + P_XS);
        float* hs  = (float*)(smraw + P_HS);

        for (int i = tid; i < CDIM * CF; i += 128) {
            const int k = i >> 3, c = i & 7;
            wfT[c * 68 + k] = w_f[i];
            wgT[c * 68 + k] = w_g[i];
        }
        for (int i = tid; i < CDIM * CDIM; i += 128) {
            const int k = i >> 6, c = i & 63;
            whT[c * 68 + k] = w_h[i];
        }
        if (tid < CF)   { bfs[tid] = b_f[tid]; bgs[tid] = b_g[tid]; }
        if (tid < CDIM) bhs[tid] = b_h[tid];

        const int cta  = blockIdx.y * gridDim.x + blockIdx.x;   // 0..255
        const int rowb = cta * 64;

        #pragma unroll 1
        for (int c2 = 0; c2 < 2; c2++) {
            const int r0 = rowb + c2 * 32;
            __syncthreads();
            for (int i = tid; i < 32 * CDIM; i += 128)
                xs[(i >> 6) * 68 + (i & 63)] = x[(size_t)(r0 + (i >> 6)) * CDIM + (i & 63)];
            __syncthreads();

            for (int idx = tid; idx < 32 * 80; idx += 128) {
                const int r = idx / 80, c = idx % 80;
                const float4* wv; float bias;
                if (c < 8)       { wv = (const float4*)(wfT + c * 68);        bias = bfs[c];      }
                else if (c < 16) { wv = (const float4*)(wgT + (c - 8) * 68);  bias = bgs[c - 8];  }
                else             { wv = (const float4*)(whT + (c - 16) * 68); bias = bhs[c - 16]; }
                const float4* xv = (const float4*)(xs + r * 68);
                float acc = bias;
                #pragma unroll
                for (int k = 0; k < 16; k++) {
                    const float4 a = xv[k], w4 = wv[k];
                    acc += a.x * w4.x + a.y * w4.y + a.z * w4.z + a.w * w4.w;
                }
                const int row = r0 + r;
                if (c < 8)       d_fb[row * CF + c] = __float2bfloat16(acc);
                else if (c < 16) d_gb[row * CF + (c - 8)] =
                                     __float2bfloat16(acc * 1.4426950408889634f);
                else             hs[(c - 16) * 33 + r] = acc;
            }
            __syncthreads();

            {
                const int bb = r0 >> 12, n0 = r0 & (NTOK - 1);
                const int ch = tid >> 1, part = (tid & 1) * 16;
                __nv_bfloat16 v[16];
                #pragma unroll
                for (int j = 0; j < 16; j++) v[j] = __float2bfloat16(hs[ch * 33 + part + j]);
                uint4* dst = (uint4*)(d_htb + ((size_t)bb * CDIM + ch) * NTOK + n0 + part);
                dst[0] = *(const uint4*)(v);
                dst[1] = *(const uint4*)(v + 8);
            }
        }
    }

    // ================= device-wide barrier =================
    __threadfence();
    __syncthreads();
    if (tid == 0) {
        const unsigned int ticket = atomicAdd(&d_bar, 1u);
        const unsigned int target = ((ticket >> 8) + 1u) << 8;   // next multiple of 256
        unsigned int v;
        do {
            asm volatile("ld.acquire.gpu.u32 %0, [%1];" : "=r"(v) : "l"(&d_bar));
        } while (v < target);
    }
    __syncthreads();

    // ================= phase 2: flash attention =================
    __nv_bfloat16* fSb = (__nv_bfloat16*)smraw;             // stage s: s*512 elems
    __nv_bfloat16* hSb = (__nv_bfloat16*)(smraw + 4096);    // stage s: s*4608 elems

    const int warp = tid >> 5;
    const int lane = tid & 31;
    const int gid  = lane >> 2;
    const int tig  = lane & 3;
    const int mat  = lane >> 3;
    const int mrow = lane & 7;

    const int b    = blockIdx.y;
    const int q0   = blockIdx.x * QPC + warp * 16;
    const int row0 = b * NTOK + q0;

    const int f_off = (mat * 8 + mrow) * CF;
    const int h_off = ((mat >> 1) * 8 + mrow) * HP + (mat & 1) * 8;

    const uint32_t ga0 = *reinterpret_cast<const uint32_t*>(d_gb + (row0 + gid) * CF + tig * 2);
    const uint32_t ga1 = *reinterpret_cast<const uint32_t*>(d_gb + (row0 + 8 + gid) * CF + tig * 2);

    float O[8][4];
    #pragma unroll
    for (int n = 0; n < 8; n++)
        #pragma unroll
        for (int j = 0; j < 4; j++) O[n][j] = 0.0f;
    float l0 = 0.0f, l1 = 0.0f;
    const float zc[4] = {0.0f, 0.0f, 0.0f, 0.0f};

    auto load_tile = [&](int t) {
        const int buf = t & (STG - 1);
        if (tid < 64)
            cp16(&fSb[buf * 512 + tid * CF], d_fb + (size_t)(b * NTOK + t * KT + tid) * CF);
        const __nv_bfloat16* hsrc = d_htb + (size_t)b * CDIM * NTOK + t * KT;
        #pragma unroll
        for (int k2 = 0; k2 < 4; k2++) {
            const int i  = tid + k2 * 128;
            const int ch = i >> 3, ck = i & 7;
            cp16(&hSb[buf * 4608 + ch * HP + ck * 8], hsrc + (size_t)ch * NTOK + ck * 8);
        }
    };

    auto process_tile = [&](int t) {
        const int buf = t & (STG - 1);
        // --- QK: S[16q x 64k] (S already in log2 domain: g pre-scaled) ---
        float S[8][4];
        {
            uint32_t fb[8];
            ldmat4(fb[0], fb[1], fb[2], fb[3], &fSb[buf * 512 + f_off]);
            ldmat4(fb[4], fb[5], fb[6], fb[7], &fSb[buf * 512 + f_off + 32 * CF]);
            #pragma unroll
            for (int n = 0; n < 8; n++) MMA1688(S[n], ga0, ga1, fb[n], zc);
        }
        // --- ex2 + row sums + pack P ---
        uint32_t P[8][2];
        #pragma unroll
        for (int n = 0; n < 8; n++) {
            const float e0 = ex2f(S[n][0]);
            const float e1 = ex2f(S[n][1]);
            const float e2 = ex2f(S[n][2]);
            const float e3 = ex2f(S[n][3]);
            l0 += e0 + e1;
            l1 += e2 + e3;
            CVT_BF16X2(P[n][0], e0, e1);
            CVT_BF16X2(P[n][1], e2, e3);
        }
        // --- PV: O += P @ H^T ---
        #pragma unroll
        for (int kk = 0; kk < 4; kk++) {
            const uint32_t a0 = P[2 * kk][0];
            const uint32_t a1 = P[2 * kk][1];
            const uint32_t a2 = P[2 * kk + 1][0];
            const uint32_t a3 = P[2 * kk + 1][1];
            #pragma unroll
            for (int np = 0; np < 4; np++) {
                uint32_t b0, b1, b2, b3;
                ldmat4(b0, b1, b2, b3, &hSb[buf * 4608 + h_off + np * 16 * HP + kk * 16]);
                MMA16816(O[2 * np],     a0, a1, a2, a3, b0, b1, O[2 * np]);
                MMA16816(O[2 * np + 1], a0, a1, a2, a3, b2, b3, O[2 * np + 1]);
            }
        }
    };

    // 2 tiles per barrier: loads for t+2,t+3 issued right after the sync,
    // landing in the stages consumed during the PREVIOUS iteration.
    load_tile(0); CP_COMMIT();
    load_tile(1); CP_COMMIT();

    #pragma unroll 1
    for (int t = 0; t < NTILE; t += 2) {
        CP_WAIT0();                  // own groups (tiles t, t+1) complete
        __syncthreads();             // everyone's copies visible; old stages free
        if (t + 2 < NTILE) { load_tile(t + 2); CP_COMMIT(); }
        if (t + 3 < NTILE) { load_tile(t + 3); CP_COMMIT(); }
        process_tile(t);
        process_tile(t + 1);
    }

    l0 += __shfl_xor_sync(0xFFFFFFFF, l0, 1);
    l0 += __shfl_xor_sync(0xFFFFFFFF, l0, 2);
    l1 += __shfl_xor_sync(0xFFFFFFFF, l1, 1);
    l1 += __shfl_xor_sync(0xFFFFFFFF, l1, 2);

    const float gm   = gamma[0];
    const float inv0 = gm / l0;
    const float inv1 = gm / l1;

    const size_t base0 = (size_t)(row0 + gid) * CDIM;
    const size_t base1 = (size_t)(row0 + 8 + gid) * CDIM;
    #pragma unroll
    for (int n = 0; n < 8; n++) {
        const int ch = n * 8 + tig * 2;
        const float2 xv0 = *reinterpret_cast<const float2*>(x + base0 + ch);
        const float2 xv1 = *reinterpret_cast<const float2*>(x + base1 + ch);
        float2 o0, o1;
        o0.x = fmaf(inv0, O[n][0], xv0.x);
        o0.y = fmaf(inv0, O[n][1], xv0.y);
        o1.x = fmaf(inv1, O[n][2], xv1.x);
        o1.y = fmaf(inv1, O[n][3], xv1.y);
        *reinterpret_cast<float2*>(out + base0 + ch) = o0;
        *reinterpret_cast<float2*>(out + base1 + ch) = o1;
    }
}

// ---------------- launch ----------------
extern "C" void kernel_launch(void* const* d_in, const int* in_sizes, int n_in,
                              void* d_out, int out_size) {
    const float* x     = (const float*)d_in[0];
    const float* w_f   = (const float*)d_in[1];
    const float* b_f   = (const float*)d_in[2];
    const float* w_g   = (const float*)d_in[3];
    const float* b_g   = (const float*)d_in[4];
    const float* w_h   = (const float*)d_in[5];
    const float* b_h   = (const float*)d_in[6];
    const float* gamma = (const float*)d_in[7];
    float* out = (float*)d_out;

    fused_kernel<<<dim3(NTOK / QPC, BATCH), 128>>>(x, w_f, b_f, w_g, b_g,
                                                   w_h, b_h, gamma, out);
}

// round 17
// speedup vs baseline: 1.1293x; 1.1293x over previous
#include <cuda_runtime.h>
#include <cuda_bf16.h>
#include <cstdint>

// Problem: B=4, H=W=64 -> N=4096, C=64, Cf=8
#define BATCH 4
#define NTOK  4096
#define CDIM  64
#define CF    8
#define BN    (BATCH * NTOK)
#define KT    64               // keys per tile
#define NTILE (NTOK / KT)      // 64
#define QPC   64               // queries per CTA (4 warps x 16)
#define HP    72               // hS pitch (elements) - conflict-free for ldmatrix
#define STG   4                // cp.async pipeline stages
#define LOG2E 1.4426950408889634f

// ---------------- scratch (no cudaMalloc allowed) ----------------
__device__ __nv_bfloat16 d_fb[BN * CF];              // keys    [B,N,8]
__device__ __nv_bfloat16 d_gb[BN * CF];              // queries [B,N,8] (pre-scaled by log2e)
__device__ __nv_bfloat16 d_htb[BATCH * CDIM * NTOK]; // values transposed [B,C,N]
__device__ unsigned int  d_bar = 0;                  // device-wide barrier ticket

#define MMA16816(d, a0, a1, a2, a3, b0, b1, c) \
    asm volatile("mma.sync.aligned.m16n8k16.row.col.f32.bf16.bf16.f32 " \
        "{%0,%1,%2,%3}, {%4,%5,%6,%7}, {%8,%9}, {%10,%11,%12,%13};" \
        : "=f"((d)[0]), "=f"((d)[1]), "=f"((d)[2]), "=f"((d)[3]) \
        : "r"(a0), "r"(a1), "r"(a2), "r"(a3), "r"(b0), "r"(b1), \
          "f"((c)[0]), "f"((c)[1]), "f"((c)[2]), "f"((c)[3]))

#define MMA1688(d, a0, a1, b0, c) \
    asm volatile("mma.sync.aligned.m16n8k8.row.col.f32.bf16.bf16.f32 " \
        "{%0,%1,%2,%3}, {%4,%5}, {%6}, {%7,%8,%9,%10};" \
        : "=f"((d)[0]), "=f"((d)[1]), "=f"((d)[2]), "=f"((d)[3]) \
        : "r"(a0), "r"(a1), "r"(b0), \
          "f"((c)[0]), "f"((c)[1]), "f"((c)[2]), "f"((c)[3]))

#define CVT_BF16X2(res, lo, hi) \
    asm("cvt.rn.bf16x2.f32 %0, %1, %2;" : "=r"(res) : "f"(hi), "f"(lo))

__device__ __forceinline__ float ex2f(float v) {
    float r;
    asm("ex2.approx.f32 %0, %1;" : "=f"(r) : "f"(v));
    return r;
}

__device__ __forceinline__ void cp16(void* dst, const void* src) {
    const uint32_t d = (uint32_t)__cvta_generic_to_shared(dst);
    asm volatile("cp.async.cg.shared.global [%0], [%1], 16;" :: "r"(d), "l"(src));
}
#define CP_COMMIT() asm volatile("cp.async.commit_group;" ::: "memory")
#define CP_WAIT2()  asm volatile("cp.async.wait_group 2;" ::: "memory")

__device__ __forceinline__ void ldmat4(uint32_t& r0, uint32_t& r1, uint32_t& r2,
                                       uint32_t& r3, const void* p) {
    const uint32_t a = (uint32_t)__cvta_generic_to_shared(p);
    asm volatile("ldmatrix.sync.aligned.m8n8.x4.shared.b16 {%0,%1,%2,%3}, [%4];"
                 : "=r"(r0), "=r"(r1), "=r"(r2), "=r"(r3) : "r"(a));
}

// shared-memory overlay (40960 bytes)
//  attn: fS stage s @ s*1024 (4x1KB), hS stage s @ 4096 + s*9216 (4x9KB)
//  proj: wS[64][80] @0 (20480B), bias[80] @20480, xs[64 rows][65] @20800 (16640B)
//        hs[64 ch][65] @0 (reuses wS region after compute)
#define SM_BYTES 40960
#define P_WS  0
#define P_BS  20480
#define P_XS  20800
#define P_HS  0

__global__ __launch_bounds__(128, 2)
void fused_kernel(const float* __restrict__ x,
                  const float* __restrict__ w_f, const float* __restrict__ b_f,
                  const float* __restrict__ w_g, const float* __restrict__ b_g,
                  const float* __restrict__ w_h, const float* __restrict__ b_h,
                  const float* __restrict__ gamma,
                  float* __restrict__ out) {
    __shared__ __align__(16) char smraw[SM_BYTES];

    const int tid = threadIdx.x;
    const int cta = blockIdx.y * gridDim.x + blockIdx.x;   // 0..255

    // ================= phase 1: projections (register-blocked) =========
    {
        float* wS = (float*)(smraw + P_WS);    // [k][80] combined f|g|h weights
        float* bS = (float*)(smraw + P_BS);    // [80]
        float* xs = (float*)(smraw + P_XS);    // [row][65]

        // combined weights: wS[k][c] ; c<8 f, c<16 g, else h
        for (int i = tid; i < 64 * 80; i += 128) {
            const int k = i / 80, c = i % 80;
            float v;
            if (c < 8)       v = w_f[k * CF + c];
            else if (c < 16) v = w_g[k * CF + (c - 8)];
            else             v = w_h[k * CDIM + (c - 16)];
            wS[k * 80 + c] = v;
        }
        if (tid < 80) {
            float v;
            if (tid < 8)       v = b_f[tid];
            else if (tid < 16) v = b_g[tid - 8];
            else               v = b_h[tid - 16];
            bS[tid] = v;
        }
        // x tile: 64 rows x 64 ch, pitch 65 — SCALAR staging (odd-row bases
        // are not 16B-aligned; float4 stores here fault). Coalesced globally,
        // stride-65 smem stores are conflict-free (65 odd).
        const int rowb = cta * 64;
        for (int i = tid; i < 64 * CDIM; i += 128)
            xs[(i >> 6) * 65 + (i & 63)] = x[(size_t)rowb * CDIM + i];
        __syncthreads();

        const int r    = tid & 63;          // row within tile
        const int half = tid >> 6;          // ch half: 0 -> ch 0..39, 1 -> 40..79
        const int cb   = half * 40;

        float acc[40];
        #pragma unroll
        for (int j = 0; j < 40; j++) acc[j] = bS[cb + j];

        #pragma unroll 2
        for (int k = 0; k < 64; k++) {
            const float xk = xs[r * 65 + k];
            const float4* wrow = (const float4*)(wS + k * 80 + cb);   // 16B-aligned: 80*4 and cb*4 multiples of 16
            #pragma unroll
            for (int j4 = 0; j4 < 10; j4++) {
                const float4 w4 = wrow[j4];
                acc[j4 * 4 + 0] = fmaf(xk, w4.x, acc[j4 * 4 + 0]);
                acc[j4 * 4 + 1] = fmaf(xk, w4.y, acc[j4 * 4 + 1]);
                acc[j4 * 4 + 2] = fmaf(xk, w4.z, acc[j4 * 4 + 2]);
                acc[j4 * 4 + 3] = fmaf(xk, w4.w, acc[j4 * 4 + 3]);
            }
        }

        const int row = rowb + r;
        if (half == 0) {
            // f = acc[0..8), g = acc[8..16) — direct stores (16B-aligned: row*8 bf16)
            __nv_bfloat16 fv[8], gv[8];
            #pragma unroll
            for (int j = 0; j < 8; j++) {
                fv[j] = __float2bfloat16(acc[j]);
                gv[j] = __float2bfloat16(acc[8 + j] * LOG2E);
            }
            *(uint4*)(d_fb + row * CF) = *(const uint4*)fv;
            *(uint4*)(d_gb + row * CF) = *(const uint4*)gv;
        }
        __syncthreads();                       // done reading wS/xs
        float* hs = (float*)(smraw + P_HS);    // [ch][65] (reuses wS region)
        if (half == 0) {
            #pragma unroll
            for (int j = 16; j < 40; j++) hs[(j - 16) * 65 + r] = acc[j];
        } else {
            #pragma unroll
            for (int j = 0; j < 40; j++) hs[(j + 24) * 65 + r] = acc[j];
        }
        __syncthreads();
        // transposed h store: ch = tid/2, 32 keys per thread (64B-aligned dst)
        {
            const int bb = rowb >> 12, n0s = rowb & (NTOK - 1);
            const int ch = tid >> 1, part = (tid & 1) * 32;
            __nv_bfloat16 v[32];
            #pragma unroll
            for (int j = 0; j < 32; j++) v[j] = __float2bfloat16(hs[ch * 65 + part + j]);
            uint4* dst = (uint4*)(d_htb + ((size_t)bb * CDIM + ch) * NTOK + n0s + part);
            #pragma unroll
            for (int q = 0; q < 4; q++) dst[q] = ((const uint4*)v)[q];
        }
    }

    // ================= device-wide barrier =================
    __threadfence();
    __syncthreads();
    if (tid == 0) {
        const unsigned int ticket = atomicAdd(&d_bar, 1u);
        const unsigned int target = ((ticket >> 8) + 1u) << 8;   // next multiple of 256
        unsigned int v;
        do {
            asm volatile("ld.acquire.gpu.u32 %0, [%1];" : "=r"(v) : "l"(&d_bar));
        } while (v < target);
    }
    __syncthreads();

    // ================= phase 2: flash attention (R13 core) =================
    __nv_bfloat16* fSb = (__nv_bfloat16*)smraw;             // stage s: s*512 elems
    __nv_bfloat16* hSb = (__nv_bfloat16*)(smraw + 4096);    // stage s: s*4608 elems

    const int warp = tid >> 5;
    const int lane = tid & 31;
    const int gid  = lane >> 2;
    const int tig  = lane & 3;
    const int mat  = lane >> 3;
    const int mrow = lane & 7;

    const int b    = blockIdx.y;
    const int q0   = blockIdx.x * QPC + warp * 16;
    const int row0 = b * NTOK + q0;

    const int f_off = (mat * 8 + mrow) * CF;
    const int h_off = ((mat >> 1) * 8 + mrow) * HP + (mat & 1) * 8;

    const uint32_t ga0 = *reinterpret_cast<const uint32_t*>(d_gb + (row0 + gid) * CF + tig * 2);
    const uint32_t ga1 = *reinterpret_cast<const uint32_t*>(d_gb + (row0 + 8 + gid) * CF + tig * 2);

    float O[8][4];
    #pragma unroll
    for (int n = 0; n < 8; n++)
        #pragma unroll
        for (int j = 0; j < 4; j++) O[n][j] = 0.0f;
    float l0 = 0.0f, l1 = 0.0f;
    const float zc[4] = {0.0f, 0.0f, 0.0f, 0.0f};

    auto load_tile = [&](int t) {
        const int buf = t & (STG - 1);
        if (tid < 64)
            cp16(&fSb[buf * 512 + tid * CF], d_fb + (size_t)(b * NTOK + t * KT + tid) * CF);
        const __nv_bfloat16* hsrc = d_htb + (size_t)b * CDIM * NTOK + t * KT;
        #pragma unroll
        for (int k2 = 0; k2 < 4; k2++) {
            const int i  = tid + k2 * 128;
            const int ch = i >> 3, ck = i & 7;
            cp16(&hSb[buf * 4608 + ch * HP + ck * 8], hsrc + (size_t)ch * NTOK + ck * 8);
        }
    };

    load_tile(0); CP_COMMIT();
    load_tile(1); CP_COMMIT();
    load_tile(2); CP_COMMIT();

    #pragma unroll 1
    for (int t = 0; t < NTILE; t++) {
        CP_WAIT2();
        __syncthreads();
        if (t + 3 < NTILE) load_tile(t + 3);
        CP_COMMIT();

        const int buf = t & (STG - 1);

        // --- QK: S[16q x 64k] (log2 domain: g pre-scaled) ---
        float S[8][4];
        {
            uint32_t fb[8];
            ldmat4(fb[0], fb[1], fb[2], fb[3], &fSb[buf * 512 + f_off]);
            ldmat4(fb[4], fb[5], fb[6], fb[7], &fSb[buf * 512 + f_off + 32 * CF]);
            #pragma unroll
            for (int n = 0; n < 8; n++) MMA1688(S[n], ga0, ga1, fb[n], zc);
        }

        // --- ex2 + row sums + pack P ---
        uint32_t P[8][2];
        #pragma unroll
        for (int n = 0; n < 8; n++) {
            const float e0 = ex2f(S[n][0]);
            const float e1 = ex2f(S[n][1]);
            const float e2 = ex2f(S[n][2]);
            const float e3 = ex2f(S[n][3]);
            l0 += e0 + e1;
            l1 += e2 + e3;
            CVT_BF16X2(P[n][0], e0, e1);
            CVT_BF16X2(P[n][1], e2, e3);
        }

        // --- PV: O += P @ H^T ---
        #pragma unroll
        for (int kk = 0; kk < 4; kk++) {
            const uint32_t a0 = P[2 * kk][0];
            const uint32_t a1 = P[2 * kk][1];
            const uint32_t a2 = P[2 * kk + 1][0];
            const uint32_t a3 = P[2 * kk + 1][1];
            #pragma unroll
            for (int np = 0; np < 4; np++) {
                uint32_t b0, b1, b2, b3;
                ldmat4(b0, b1, b2, b3, &hSb[buf * 4608 + h_off + np * 16 * HP + kk * 16]);
                MMA16816(O[2 * np],     a0, a1, a2, a3, b0, b1, O[2 * np]);
                MMA16816(O[2 * np + 1], a0, a1, a2, a3, b2, b3, O[2 * np + 1]);
            }
        }
    }

    l0 += __shfl_xor_sync(0xFFFFFFFF, l0, 1);
    l0 += __shfl_xor_sync(0xFFFFFFFF, l0, 2);
    l1 += __shfl_xor_sync(0xFFFFFFFF, l1, 1);
    l1 += __shfl_xor_sync(0xFFFFFFFF, l1, 2);

    const float gm   = gamma[0];
    const float inv0 = gm / l0;
    const float inv1 = gm / l1;

    const size_t base0 = (size_t)(row0 + gid) * CDIM;
    const size_t base1 = (size_t)(row0 + 8 + gid) * CDIM;
    #pragma unroll
    for (int n = 0; n < 8; n++) {
        const int ch = n * 8 + tig * 2;
        const float2 xv0 = *reinterpret_cast<const float2*>(x + base0 + ch);
        const float2 xv1 = *reinterpret_cast<const float2*>(x + base1 + ch);
        float2 o0, o1;
        o0.x = fmaf(inv0, O[n][0], xv0.x);
        o0.y = fmaf(inv0, O[n][1], xv0.y);
        o1.x = fmaf(inv1, O[n][2], xv1.x);
        o1.y = fmaf(inv1, O[n][3], xv1.y);
        *reinterpret_cast<float2*>(out + base0 + ch) = o0;
        *reinterpret_cast<float2*>(out + base1 + ch) = o1;
    }
}

// ---------------- launch ----------------
extern "C" void kernel_launch(void* const* d_in, const int* in_sizes, int n_in,
                              void* d_out, int out_size) {
    const float* x     = (const float*)d_in[0];
    const float* w_f   = (const float*)d_in[1];
    const float* b_f   = (const float*)d_in[2];
    const float* w_g   = (const float*)d_in[3];
    const float* b_g   = (const float*)d_in[4];
    const float* w_h   = (const float*)d_in[5];
    const float* b_h   = (const float*)d_in[6];
    const float* gamma = (const float*)d_in[7];
    float* out = (float*)d_out;

    fused_kernel<<<dim3(NTOK / QPC, BATCH), 128>>>(x, w_f, b_f, w_g, b_g,
                                                   w_h, b_h, gamma, out);
}